// round 3
// baseline (speedup 1.0000x reference)
#include <cuda_runtime.h>
#include <cuda_bf16.h>

#define BB  64
#define TT  2048
#define BT  (BB*TT)          // 131072 rows
#define CIN 44
#define DD  512
#define DC  640
#define RED 160
#define EPSF 1e-5f

// ---- scratch (device globals; no allocation allowed) ----
__device__ float  g_z[(size_t)BT * DC];      // z, later h (in-place)
__device__ float  g_yavg[BB * DC];
__device__ float  g_se[BB * DC];
__device__ float2 g_gn[BB * 8];

__device__ __forceinline__ float sigmoidf_(float x) { return 1.f / (1.f + __expf(-x)); }

// =====================================================================
// Stage 1: grouped projections  x[BT,44] -> z[BT,640]
// 32 rows per block; hidden activations staged in smem.
// =====================================================================
__global__ void __launch_bounds__(256) stage1_kernel(
    const float* __restrict__ x,
    const float* __restrict__ hw1, const float* __restrict__ hb1,
    const float* __restrict__ hw2, const float* __restrict__ hb2,
    const float* __restrict__ lw1, const float* __restrict__ lb1,
    const float* __restrict__ lw2, const float* __restrict__ lb2,
    const float* __restrict__ ew1, const float* __restrict__ eb1,
    const float* __restrict__ ew2, const float* __restrict__ eb2)
{
    extern __shared__ float sm[];
    float* xs = sm;               // [32][44]
    float* hs = sm + 32 * CIN;    // [32][640]
    const int tid = threadIdx.x;
    const long long r0 = (long long)blockIdx.x * 32;

    for (int i = tid; i < 32 * CIN; i += 256)
        xs[i] = x[r0 * CIN + i];
    __syncthreads();

    // phase A: hidden = silu(x_slice @ W1 + b1)
    for (int idx = tid; idx < 32 * DC; idx += 256) {
        const int r = idx / DC, c = idx - r * DC;
        float acc;
        if (c < 256) {
            acc = hb1[c];
            #pragma unroll
            for (int k = 0; k < 14; k++) acc = fmaf(xs[r*CIN + k],      hw1[k*256 + c],       acc);
        } else if (c < 512) {
            const int cc = c - 256;
            acc = lb1[cc];
            #pragma unroll
            for (int k = 0; k < 22; k++) acc = fmaf(xs[r*CIN + 14 + k], lw1[k*256 + cc],      acc);
        } else {
            const int cc = c - 512;
            acc = eb1[cc];
            #pragma unroll
            for (int k = 0; k < 8; k++)  acc = fmaf(xs[r*CIN + 36 + k], ew1[k*128 + cc],      acc);
        }
        hs[idx] = acc * sigmoidf_(acc);   // silu
    }
    __syncthreads();

    // phase B: z = hidden @ W2 + b2 ; 4x4 register tile per thread
    const int tx = tid & 31, ty = tid >> 5;
    const int rbase = ty * 4;
    for (int chunk = 0; chunk < 5; chunk++) {
        const int c0 = chunk * 128 + tx * 4;
        const float *W2, *bias; int cw, K2, ldw, koff;
        if (chunk < 2)      { W2 = hw2; bias = hb2; cw = c0;       K2 = 256; ldw = 256; koff = 0;   }
        else if (chunk < 4) { W2 = lw2; bias = lb2; cw = c0 - 256; K2 = 256; ldw = 256; koff = 256; }
        else                { W2 = ew2; bias = eb2; cw = c0 - 512; K2 = 128; ldw = 128; koff = 512; }
        const float4 bv = *(const float4*)(bias + cw);
        float acc[4][4];
        #pragma unroll
        for (int i = 0; i < 4; i++) { acc[i][0]=bv.x; acc[i][1]=bv.y; acc[i][2]=bv.z; acc[i][3]=bv.w; }
        #pragma unroll 4
        for (int k = 0; k < K2; k++) {
            const float4 w = *(const float4*)(W2 + (size_t)k * ldw + cw);
            #pragma unroll
            for (int i = 0; i < 4; i++) {
                const float a = hs[(rbase + i) * DC + koff + k];
                acc[i][0] = fmaf(a, w.x, acc[i][0]);
                acc[i][1] = fmaf(a, w.y, acc[i][1]);
                acc[i][2] = fmaf(a, w.z, acc[i][2]);
                acc[i][3] = fmaf(a, w.w, acc[i][3]);
            }
        }
        #pragma unroll
        for (int i = 0; i < 4; i++)
            *(float4*)(&g_z[(r0 + rbase + i) * DC + c0]) =
                make_float4(acc[i][0], acc[i][1], acc[i][2], acc[i][3]);
    }
}

// =====================================================================
// SE: mean over T per (batch, channel)
// =====================================================================
__global__ void __launch_bounds__(256) se_reduce_kernel()
{
    __shared__ float ssum[256];
    const int b = blockIdx.x;
    const int c = blockIdx.y * 128 + (threadIdx.x & 127);
    const int half = threadIdx.x >> 7;
    float s = 0.f;
    const int t0 = half * 1024;
    for (int t = t0; t < t0 + 1024; t++)
        s += g_z[((long long)b * TT + t) * DC + c];
    ssum[threadIdx.x] = s;
    __syncthreads();
    if (half == 0)
        g_yavg[b * DC + c] = (ssum[threadIdx.x] + ssum[threadIdx.x + 128]) * (1.f / TT);
}

__global__ void __launch_bounds__(256) se_mlp_kernel(
    const float* __restrict__ se_w1, const float* __restrict__ se_w2)
{
    __shared__ float ys[DC];
    __shared__ float hid[RED];
    const int b = blockIdx.x, tid = threadIdx.x;
    for (int c = tid; c < DC; c += 256) ys[c] = g_yavg[b * DC + c];
    __syncthreads();
    if (tid < RED) {
        float acc = 0.f;
        for (int c = 0; c < DC; c++) acc = fmaf(ys[c], se_w1[c * RED + tid], acc);
        hid[tid] = fmaxf(acc, 0.f);
    }
    __syncthreads();
    for (int c = tid; c < DC; c += 256) {
        float acc = 0.f;
        for (int j = 0; j < RED; j++) acc = fmaf(hid[j], se_w2[j * DC + c], acc);
        g_se[b * DC + c] = sigmoidf_(acc);
    }
}

// =====================================================================
// SymmetryGate: g = sigmoid(z_se@gw+gb), p = z_se@pw+pb,
//               h = g*p + (1-g)*z_se   (written in place over g_z)
// =====================================================================
__global__ void __launch_bounds__(256) gate_kernel(
    const float* __restrict__ gw, const float* __restrict__ gb,
    const float* __restrict__ pw, const float* __restrict__ pb)
{
    extern __shared__ float sm[];
    float* zs  = sm;            // [32][640]  (z_se)
    float* ses = sm + 32 * DC;  // [640]
    const int tid = threadIdx.x;
    const long long r0 = (long long)blockIdx.x * 32;
    const int b = (int)(r0 / TT);     // 32 | 2048, so block never straddles a batch

    for (int c = tid; c < DC; c += 256) ses[c] = g_se[b * DC + c];
    for (int i = tid; i < 32 * DC; i += 256) zs[i] = g_z[r0 * DC + i];
    __syncthreads();
    for (int i = tid; i < 32 * DC; i += 256) {
        const int r = i / DC;
        zs[i] *= ses[i - r * DC];
    }
    __syncthreads();

    const int tx = tid & 31, ty = tid >> 5;
    const int rbase = ty * 4;
    for (int chunk = 0; chunk < 5; chunk++) {
        const int c0 = chunk * 128 + tx * 4;
        const float4 gbv = *(const float4*)(gb + c0);
        const float4 pbv = *(const float4*)(pb + c0);
        float ga[4][4], pa[4][4];
        #pragma unroll
        for (int i = 0; i < 4; i++) {
            ga[i][0]=gbv.x; ga[i][1]=gbv.y; ga[i][2]=gbv.z; ga[i][3]=gbv.w;
            pa[i][0]=pbv.x; pa[i][1]=pbv.y; pa[i][2]=pbv.z; pa[i][3]=pbv.w;
        }
        #pragma unroll 2
        for (int k = 0; k < DC; k++) {
            const float4 wg = *(const float4*)(gw + (size_t)k * DC + c0);
            const float4 wp = *(const float4*)(pw + (size_t)k * DC + c0);
            #pragma unroll
            for (int i = 0; i < 4; i++) {
                const float a = zs[(rbase + i) * DC + k];
                ga[i][0] = fmaf(a, wg.x, ga[i][0]);
                ga[i][1] = fmaf(a, wg.y, ga[i][1]);
                ga[i][2] = fmaf(a, wg.z, ga[i][2]);
                ga[i][3] = fmaf(a, wg.w, ga[i][3]);
                pa[i][0] = fmaf(a, wp.x, pa[i][0]);
                pa[i][1] = fmaf(a, wp.y, pa[i][1]);
                pa[i][2] = fmaf(a, wp.z, pa[i][2]);
                pa[i][3] = fmaf(a, wp.w, pa[i][3]);
            }
        }
        #pragma unroll
        for (int i = 0; i < 4; i++) {
            float4 hv;
            float* hp = (float*)&hv;
            #pragma unroll
            for (int j = 0; j < 4; j++) {
                const float zse = zs[(rbase + i) * DC + c0 + j];
                const float s = sigmoidf_(ga[i][j]);
                hp[j] = s * pa[i][j] + (1.f - s) * zse;
            }
            *(float4*)(&g_z[(r0 + rbase + i) * DC + c0]) = hv;
        }
    }
}

// =====================================================================
// LayerNorm over DC per row (warp per row), in place on g_z
// =====================================================================
__global__ void __launch_bounds__(256) ln_kernel(
    const float* __restrict__ ln_w, const float* __restrict__ ln_b)
{
    const long long r = (long long)blockIdx.x * 8 + (threadIdx.x >> 5);
    const int lane = threadIdx.x & 31;
    float v[20];
    float s = 0.f, s2 = 0.f;
    #pragma unroll
    for (int j = 0; j < 20; j++) {
        v[j] = g_z[r * DC + lane + j * 32];
        s += v[j]; s2 += v[j] * v[j];
    }
    #pragma unroll
    for (int o = 16; o > 0; o >>= 1) {
        s  += __shfl_xor_sync(0xffffffff, s,  o);
        s2 += __shfl_xor_sync(0xffffffff, s2, o);
    }
    const float mu = s * (1.f / DC);
    const float var = fmaxf(s2 * (1.f / DC) - mu * mu, 0.f);
    const float rstd = rsqrtf(var + EPSF);
    #pragma unroll
    for (int j = 0; j < 20; j++) {
        const int c = lane + j * 32;
        g_z[r * DC + c] = (v[j] - mu) * rstd * ln_w[c] + ln_b[c];
    }
}

// =====================================================================
// Output projection: out = h @ ow + ob  (pre-GroupNorm, into d_out)
// =====================================================================
__global__ void __launch_bounds__(256) out_kernel(
    const float* __restrict__ ow, const float* __restrict__ ob,
    float* __restrict__ out)
{
    extern __shared__ float hsm[];   // [32][640]
    const int tid = threadIdx.x;
    const long long r0 = (long long)blockIdx.x * 32;
    for (int i = tid; i < 32 * DC; i += 256) hsm[i] = g_z[r0 * DC + i];
    __syncthreads();

    const int tx = tid & 31, ty = tid >> 5;
    const int rbase = ty * 4;
    for (int chunk = 0; chunk < 4; chunk++) {
        const int c0 = chunk * 128 + tx * 4;
        const float4 bv = *(const float4*)(ob + c0);
        float acc[4][4];
        #pragma unroll
        for (int i = 0; i < 4; i++) { acc[i][0]=bv.x; acc[i][1]=bv.y; acc[i][2]=bv.z; acc[i][3]=bv.w; }
        #pragma unroll 4
        for (int k = 0; k < DC; k++) {
            const float4 w = *(const float4*)(ow + (size_t)k * DD + c0);
            #pragma unroll
            for (int i = 0; i < 4; i++) {
                const float a = hsm[(rbase + i) * DC + k];
                acc[i][0] = fmaf(a, w.x, acc[i][0]);
                acc[i][1] = fmaf(a, w.y, acc[i][1]);
                acc[i][2] = fmaf(a, w.z, acc[i][2]);
                acc[i][3] = fmaf(a, w.w, acc[i][3]);
            }
        }
        #pragma unroll
        for (int i = 0; i < 4; i++)
            *(float4*)(&out[(r0 + rbase + i) * DD + c0]) =
                make_float4(acc[i][0], acc[i][1], acc[i][2], acc[i][3]);
    }
}

// =====================================================================
// GroupNorm(8, 512): stats per (batch, group) over (T, 64 chans)
// =====================================================================
__global__ void __launch_bounds__(256) gn_stats_kernel(const float* __restrict__ out)
{
    __shared__ float s1[256], s2a[256];
    const int b = blockIdx.x, g = blockIdx.y;
    float s = 0.f, s2 = 0.f;
    for (int idx = threadIdx.x; idx < TT * 64; idx += 256) {
        const int t = idx >> 6, c = idx & 63;
        const float v = out[((long long)b * TT + t) * DD + g * 64 + c];
        s += v; s2 += v * v;
    }
    s1[threadIdx.x] = s; s2a[threadIdx.x] = s2;
    __syncthreads();
    for (int o = 128; o > 0; o >>= 1) {
        if (threadIdx.x < o) { s1[threadIdx.x] += s1[threadIdx.x + o]; s2a[threadIdx.x] += s2a[threadIdx.x + o]; }
        __syncthreads();
    }
    if (threadIdx.x == 0) {
        const float inv = 1.f / (TT * 64.f);
        const float m = s1[0] * inv;
        const float var = fmaxf(s2a[0] * inv - m * m, 0.f);
        g_gn[b * 8 + g] = make_float2(m, rsqrtf(var + EPSF));
    }
}

__global__ void __launch_bounds__(256) gn_apply_kernel(
    float* __restrict__ out, const float* __restrict__ gn_w, const float* __restrict__ gn_b)
{
    const long long total4 = (long long)BT * DD / 4;
    for (long long i4 = (long long)blockIdx.x * blockDim.x + threadIdx.x;
         i4 < total4; i4 += (long long)gridDim.x * blockDim.x) {
        const long long i = i4 * 4;
        const int c = (int)(i & (DD - 1));
        const int b = (int)(i >> 20);          // / (T*D) = / 2^20
        const int g = c >> 6;
        const float2 mg = g_gn[b * 8 + g];
        float4 v = *(float4*)(out + i);
        v.x = (v.x - mg.x) * mg.y * gn_w[c]     + gn_b[c];
        v.y = (v.y - mg.x) * mg.y * gn_w[c + 1] + gn_b[c + 1];
        v.z = (v.z - mg.x) * mg.y * gn_w[c + 2] + gn_b[c + 2];
        v.w = (v.w - mg.x) * mg.y * gn_w[c + 3] + gn_b[c + 3];
        *(float4*)(out + i) = v;
    }
}

// =====================================================================
// launch
// =====================================================================
extern "C" void kernel_launch(void* const* d_in, const int* in_sizes, int n_in,
                              void* d_out, int out_size)
{
    const float* x    = (const float*)d_in[0];
    const float* hw1  = (const float*)d_in[1];
    const float* hb1  = (const float*)d_in[2];
    const float* hw2  = (const float*)d_in[3];
    const float* hb2  = (const float*)d_in[4];
    const float* lw1  = (const float*)d_in[5];
    const float* lb1  = (const float*)d_in[6];
    const float* lw2  = (const float*)d_in[7];
    const float* lb2  = (const float*)d_in[8];
    const float* ew1  = (const float*)d_in[9];
    const float* eb1  = (const float*)d_in[10];
    const float* ew2  = (const float*)d_in[11];
    const float* eb2  = (const float*)d_in[12];
    const float* sew1 = (const float*)d_in[13];
    const float* sew2 = (const float*)d_in[14];
    const float* gw   = (const float*)d_in[15];
    const float* gb   = (const float*)d_in[16];
    const float* pw   = (const float*)d_in[17];
    const float* pb   = (const float*)d_in[18];
    const float* lnw  = (const float*)d_in[19];
    const float* lnb  = (const float*)d_in[20];
    const float* ow   = (const float*)d_in[21];
    const float* ob   = (const float*)d_in[22];
    const float* gnw  = (const float*)d_in[23];
    const float* gnb  = (const float*)d_in[24];
    float* out = (float*)d_out;

    const int SMEM1 = (32 * CIN + 32 * DC) * 4;   // 87552
    const int SMEMG = (32 * DC + DC) * 4;         // 84480
    const int SMEMO = (32 * DC) * 4;              // 81920
    // Idempotent; attribute persists across calls. Errors (if any mid-capture) ignored.
    cudaFuncSetAttribute(stage1_kernel, cudaFuncAttributeMaxDynamicSharedMemorySize, SMEM1);
    cudaFuncSetAttribute(gate_kernel,   cudaFuncAttributeMaxDynamicSharedMemorySize, SMEMG);
    cudaFuncSetAttribute(out_kernel,    cudaFuncAttributeMaxDynamicSharedMemorySize, SMEMO);

    stage1_kernel<<<BT / 32, 256, SMEM1>>>(x, hw1, hb1, hw2, hb2,
                                           lw1, lb1, lw2, lb2,
                                           ew1, eb1, ew2, eb2);
    se_reduce_kernel<<<dim3(BB, 5), 256>>>();
    se_mlp_kernel<<<BB, 256>>>(sew1, sew2);
    gate_kernel<<<BT / 32, 256, SMEMG>>>(gw, gb, pw, pb);
    ln_kernel<<<BT / 8, 256>>>(lnw, lnb);
    out_kernel<<<BT / 32, 256, SMEMO>>>(ow, ob, out);
    gn_stats_kernel<<<dim3(BB, 8), 256>>>(out);
    gn_apply_kernel<<<4096, 256>>>(out, gnw, gnb);
}

// round 11
// speedup vs baseline: 2.8835x; 2.8835x over previous
#include <cuda_runtime.h>
#include <cuda_bf16.h>
#include <cstdint>

#define BB  64
#define TT  2048
#define BT  (BB*TT)          // 131072 rows
#define CIN 44
#define DD  512
#define DC  640
#define RED 160
#define EPSF 1e-5f
#define WROWS 1792           // 640 (gw) + 640 (pw) + 512 (ow), transposed [N][K]

// ---- scratch (device globals; no allocation allowed) ----
__device__ float  g_z[(size_t)BT * DC];              // z (stage1 output)
__device__ float  g_gp[(size_t)BT * 1280];           // raw gate/proj logits
__device__ float  g_yavg[BB * DC];
__device__ float  g_se[BB * DC];
__device__ float2 g_gn[BB * 8];
__device__ __nv_bfloat16 g_ahi[(size_t)BT * DC];     // activation split hi
__device__ __nv_bfloat16 g_alo[(size_t)BT * DC];     // activation split lo
__device__ __nv_bfloat16 g_whi[(size_t)WROWS * DC];  // weightsT split hi
__device__ __nv_bfloat16 g_wlo[(size_t)WROWS * DC];  // weightsT split lo

extern __shared__ char smem_raw[];

__device__ __forceinline__ float sigmoidf_(float x) { return 1.f / (1.f + __expf(-x)); }

__device__ __forceinline__ uint32_t smem_u32(const void* p) {
    uint32_t a;
    asm("{ .reg .u64 t; cvta.to.shared.u64 t, %1; cvt.u32.u64 %0, t; }" : "=r"(a) : "l"(p));
    return a;
}
__device__ __forceinline__ void cp16(uint32_t s, const void* g) {
    asm volatile("cp.async.cg.shared.global [%0], [%1], 16;" :: "r"(s), "l"(g));
}
#define CP_COMMIT() asm volatile("cp.async.commit_group;" ::: "memory")
#define CP_WAIT1()  asm volatile("cp.async.wait_group 1;" ::: "memory")
#define CP_WAIT0()  asm volatile("cp.async.wait_group 0;" ::: "memory")

__device__ __forceinline__ void mma16816(float* d, const uint32_t* a, const uint32_t* b) {
    asm volatile(
        "mma.sync.aligned.m16n8k16.row.col.f32.bf16.bf16.f32 "
        "{%0,%1,%2,%3}, {%4,%5,%6,%7}, {%8,%9}, {%0,%1,%2,%3};"
        : "+f"(d[0]), "+f"(d[1]), "+f"(d[2]), "+f"(d[3])
        : "r"(a[0]), "r"(a[1]), "r"(a[2]), "r"(a[3]), "r"(b[0]), "r"(b[1]));
}

// =====================================================================
// Stage 1: grouped projections  x[BT,44] -> z[BT,640]  (SIMT)
// =====================================================================
__global__ void __launch_bounds__(256) stage1_kernel(
    const float* __restrict__ x,
    const float* __restrict__ hw1, const float* __restrict__ hb1,
    const float* __restrict__ hw2, const float* __restrict__ hb2,
    const float* __restrict__ lw1, const float* __restrict__ lb1,
    const float* __restrict__ lw2, const float* __restrict__ lb2,
    const float* __restrict__ ew1, const float* __restrict__ eb1,
    const float* __restrict__ ew2, const float* __restrict__ eb2)
{
    float* sm = (float*)smem_raw;
    float* xs = sm;               // [32][44]
    float* hs = sm + 32 * CIN;    // [32][640]
    const int tid = threadIdx.x;
    const long long r0 = (long long)blockIdx.x * 32;

    for (int i = tid; i < 32 * CIN; i += 256)
        xs[i] = x[r0 * CIN + i];
    __syncthreads();

    for (int idx = tid; idx < 32 * DC; idx += 256) {
        const int r = idx / DC, c = idx - r * DC;
        float acc;
        if (c < 256) {
            acc = hb1[c];
            #pragma unroll
            for (int k = 0; k < 14; k++) acc = fmaf(xs[r*CIN + k],      hw1[k*256 + c],  acc);
        } else if (c < 512) {
            const int cc = c - 256;
            acc = lb1[cc];
            #pragma unroll
            for (int k = 0; k < 22; k++) acc = fmaf(xs[r*CIN + 14 + k], lw1[k*256 + cc], acc);
        } else {
            const int cc = c - 512;
            acc = eb1[cc];
            #pragma unroll
            for (int k = 0; k < 8; k++)  acc = fmaf(xs[r*CIN + 36 + k], ew1[k*128 + cc], acc);
        }
        hs[idx] = acc * sigmoidf_(acc);
    }
    __syncthreads();

    const int tx = tid & 31, ty = tid >> 5;
    const int rbase = ty * 4;
    for (int chunk = 0; chunk < 5; chunk++) {
        const int c0 = chunk * 128 + tx * 4;
        const float *W2, *bias; int cw, K2, ldw, koff;
        if (chunk < 2)      { W2 = hw2; bias = hb2; cw = c0;       K2 = 256; ldw = 256; koff = 0;   }
        else if (chunk < 4) { W2 = lw2; bias = lb2; cw = c0 - 256; K2 = 256; ldw = 256; koff = 256; }
        else                { W2 = ew2; bias = eb2; cw = c0 - 512; K2 = 128; ldw = 128; koff = 512; }
        const float4 bv = *(const float4*)(bias + cw);
        float acc[4][4];
        #pragma unroll
        for (int i = 0; i < 4; i++) { acc[i][0]=bv.x; acc[i][1]=bv.y; acc[i][2]=bv.z; acc[i][3]=bv.w; }
        #pragma unroll 4
        for (int k = 0; k < K2; k++) {
            const float4 w = *(const float4*)(W2 + (size_t)k * ldw + cw);
            #pragma unroll
            for (int i = 0; i < 4; i++) {
                const float a = hs[(rbase + i) * DC + koff + k];
                acc[i][0] = fmaf(a, w.x, acc[i][0]);
                acc[i][1] = fmaf(a, w.y, acc[i][1]);
                acc[i][2] = fmaf(a, w.z, acc[i][2]);
                acc[i][3] = fmaf(a, w.w, acc[i][3]);
            }
        }
        #pragma unroll
        for (int i = 0; i < 4; i++)
            *(float4*)(&g_z[(r0 + rbase + i) * DC + c0]) =
                make_float4(acc[i][0], acc[i][1], acc[i][2], acc[i][3]);
    }
}

// =====================================================================
// SE: mean over T per (batch, channel)  +  tiny MLP
// =====================================================================
__global__ void __launch_bounds__(256) se_reduce_kernel()
{
    __shared__ float ssum[256];
    const int b = blockIdx.x;
    const int c = blockIdx.y * 128 + (threadIdx.x & 127);
    const int half = threadIdx.x >> 7;
    float s = 0.f;
    const int t0 = half * 1024;
    for (int t = t0; t < t0 + 1024; t++)
        s += g_z[((long long)b * TT + t) * DC + c];
    ssum[threadIdx.x] = s;
    __syncthreads();
    if (half == 0)
        g_yavg[b * DC + c] = (ssum[threadIdx.x] + ssum[threadIdx.x + 128]) * (1.f / TT);
}

__global__ void __launch_bounds__(256) se_mlp_kernel(
    const float* __restrict__ se_w1, const float* __restrict__ se_w2)
{
    __shared__ float ys[DC];
    __shared__ float hid[RED];
    const int b = blockIdx.x, tid = threadIdx.x;
    for (int c = tid; c < DC; c += 256) ys[c] = g_yavg[b * DC + c];
    __syncthreads();
    if (tid < RED) {
        float acc = 0.f;
        for (int c = 0; c < DC; c++) acc = fmaf(ys[c], se_w1[c * RED + tid], acc);
        hid[tid] = fmaxf(acc, 0.f);
    }
    __syncthreads();
    for (int c = tid; c < DC; c += 256) {
        float acc = 0.f;
        for (int j = 0; j < RED; j++) acc = fmaf(hid[j], se_w2[j * DC + c], acc);
        g_se[b * DC + c] = sigmoidf_(acc);
    }
}

// =====================================================================
// prep_w: transpose + bf16-split weights into combined [1792][640]
// =====================================================================
__global__ void __launch_bounds__(256) prep_w_kernel(
    const float* __restrict__ gw, const float* __restrict__ pw, const float* __restrict__ ow)
{
    const int idx = blockIdx.x * 256 + threadIdx.x;
    if (idx >= WROWS * DC) return;
    const int n = idx / DC, k = idx - n * DC;
    float v;
    if (n < 640)       v = gw[(size_t)k * DC + n];
    else if (n < 1280) v = pw[(size_t)k * DC + (n - 640)];
    else               v = ow[(size_t)k * DD + (n - 1280)];
    const __nv_bfloat16 hi = __float2bfloat16(v);
    g_whi[idx] = hi;
    g_wlo[idx] = __float2bfloat16(v - __bfloat162float(hi));
}

// =====================================================================
// prep_a: z_se = z * se  -> bf16 hi/lo split
// =====================================================================
__global__ void __launch_bounds__(256) prep_a_kernel()
{
    const size_t total4 = (size_t)BT * DC / 4;
    for (size_t i4 = (size_t)blockIdx.x * 256 + threadIdx.x; i4 < total4;
         i4 += (size_t)gridDim.x * 256) {
        const size_t i = i4 * 4;
        const int r = (int)(i / DC);
        const int b = r >> 11;
        const int c = (int)(i - (size_t)r * DC);
        const float4 v = *(const float4*)(g_z + i);
        const float* se = g_se + b * DC + c;
        const float z0 = v.x * se[0], z1 = v.y * se[1], z2 = v.z * se[2], z3 = v.w * se[3];
        const __nv_bfloat16 h0 = __float2bfloat16(z0), h1 = __float2bfloat16(z1);
        const __nv_bfloat16 h2 = __float2bfloat16(z2), h3 = __float2bfloat16(z3);
        __nv_bfloat162* ph = (__nv_bfloat162*)(g_ahi + i);
        ph[0] = __halves2bfloat162(h0, h1);
        ph[1] = __halves2bfloat162(h2, h3);
        __nv_bfloat162* pl = (__nv_bfloat162*)(g_alo + i);
        pl[0] = __halves2bfloat162(__float2bfloat16(z0 - __bfloat162float(h0)),
                                   __float2bfloat16(z1 - __bfloat162float(h1)));
        pl[1] = __halves2bfloat162(__float2bfloat16(z2 - __bfloat162float(h2)),
                                   __float2bfloat16(z3 - __bfloat162float(h3)));
    }
}

// =====================================================================
// Generic split-bf16 HMMA GEMM:
//   C[r0:r0+128, n0:n0+128] = A[r,:640] @ W[wrow0+n, :640]^T (+bias)
//   A = g_ahi+g_alo, W = g_whi+g_wlo, 3-term split, fp32 accum.
//   which=0 -> C = g_gp (ldc 1280, no bias); which=1 -> C = Cext (+bias)
// SMEM: rows padded to 72 halves -> conflict-free fragment LDS.
// =====================================================================
#define GEMM_SMEM (2 * 36864 * 2)   // 147456 B

__global__ void __launch_bounds__(256, 1) gemm_kernel(
    int wrow0, int which, float* __restrict__ Cext, int ldc,
    const float* __restrict__ bias)
{
    __nv_bfloat16* sm = (__nv_bfloat16*)smem_raw;
    const int tid = threadIdx.x;
    const int lane = tid & 31, wid = tid >> 5;
    const int warp_m = wid >> 1, warp_n = wid & 1;
    const int g = lane >> 2, tg = lane & 3;
    const int n0 = blockIdx.x * 128;
    const long long r0 = (long long)blockIdx.y * 128;
    float* __restrict__ C = which ? Cext : g_gp;

    float acc[2][8][4];
    #pragma unroll
    for (int i = 0; i < 2; i++)
        #pragma unroll
        for (int j = 0; j < 8; j++)
            #pragma unroll
            for (int v = 0; v < 4; v++) acc[i][j][v] = 0.f;

    auto loads = [&](int chunk) {
        const int st = chunk & 1;
        const int kc = chunk * 64;
        __nv_bfloat16* dst = sm + st * 36864;
        #pragma unroll
        for (int q = 0; q < 4; q++) {   // 0:Ahi 1:Alo 2:Bhi 3:Blo
            const __nv_bfloat16* src = (q == 0) ? g_ahi : (q == 1) ? g_alo
                                     : (q == 2) ? g_whi : g_wlo;
            const long long rowbase = (q < 2) ? r0 : (long long)(wrow0 + n0);
            #pragma unroll
            for (int jj = 0; jj < 4; jj++) {
                const int t = tid + jj * 256;
                const int row = t >> 3, seg = t & 7;
                cp16(smem_u32(dst + q * 9216 + row * 72 + seg * 8),
                     src + (rowbase + row) * DC + kc + seg * 8);
            }
        }
        CP_COMMIT();
    };

    loads(0);
    for (int c = 0; c < 10; c++) {
        if (c < 9) { loads(c + 1); CP_WAIT1(); } else { CP_WAIT0(); }
        __syncthreads();
        const __nv_bfloat16* sA  = sm + (c & 1) * 36864;
        const __nv_bfloat16* sAl = sA + 9216;
        const __nv_bfloat16* sB  = sA + 18432;
        const __nv_bfloat16* sBl = sA + 27648;
        #pragma unroll
        for (int kk = 0; kk < 64; kk += 16) {
            uint32_t ah[2][4], al[2][4], bh[8][2], bl[8][2];
            #pragma unroll
            for (int i = 0; i < 2; i++) {
                const __nv_bfloat16* p = sA  + (warp_m*32 + i*16 + g)*72 + kk + 2*tg;
                const __nv_bfloat16* q = sAl + (warp_m*32 + i*16 + g)*72 + kk + 2*tg;
                ah[i][0] = *(const uint32_t*)p;
                ah[i][1] = *(const uint32_t*)(p + 8*72);
                ah[i][2] = *(const uint32_t*)(p + 8);
                ah[i][3] = *(const uint32_t*)(p + 8*72 + 8);
                al[i][0] = *(const uint32_t*)q;
                al[i][1] = *(const uint32_t*)(q + 8*72);
                al[i][2] = *(const uint32_t*)(q + 8);
                al[i][3] = *(const uint32_t*)(q + 8*72 + 8);
            }
            #pragma unroll
            for (int j = 0; j < 8; j++) {
                const __nv_bfloat16* p = sB  + (warp_n*64 + j*8 + g)*72 + kk + 2*tg;
                const __nv_bfloat16* q = sBl + (warp_n*64 + j*8 + g)*72 + kk + 2*tg;
                bh[j][0] = *(const uint32_t*)p;
                bh[j][1] = *(const uint32_t*)(p + 8);
                bl[j][0] = *(const uint32_t*)q;
                bl[j][1] = *(const uint32_t*)(q + 8);
            }
            #pragma unroll
            for (int i = 0; i < 2; i++)
                #pragma unroll
                for (int j = 0; j < 8; j++) mma16816(acc[i][j], ah[i], bh[j]);
            #pragma unroll
            for (int i = 0; i < 2; i++)
                #pragma unroll
                for (int j = 0; j < 8; j++) mma16816(acc[i][j], ah[i], bl[j]);
            #pragma unroll
            for (int i = 0; i < 2; i++)
                #pragma unroll
                for (int j = 0; j < 8; j++) mma16816(acc[i][j], al[i], bh[j]);
        }
        __syncthreads();
    }

    // epilogue
    #pragma unroll
    for (int i = 0; i < 2; i++) {
        const long long r = r0 + warp_m*32 + i*16 + g;
        #pragma unroll
        for (int j = 0; j < 8; j++) {
            const int cc = n0 + warp_n*64 + j*8 + 2*tg;
            float b0 = 0.f, b1 = 0.f;
            if (which) { b0 = bias[cc]; b1 = bias[cc + 1]; }
            *(float2*)(&C[(size_t)r * ldc + cc]) =
                make_float2(acc[i][j][0] + b0, acc[i][j][1] + b1);
            *(float2*)(&C[(size_t)(r + 8) * ldc + cc]) =
                make_float2(acc[i][j][2] + b0, acc[i][j][3] + b1);
        }
    }
}

// =====================================================================
// GLU + LayerNorm fused (warp per row):
//   g = sigmoid(gp[:,c]+gb), p = gp[:,640+c]+pb, zse = ahi+alo
//   h = g*p + (1-g)*zse ; LN(h) -> bf16 hi/lo into g_ahi/g_alo
// =====================================================================
__global__ void __launch_bounds__(256) glu_ln_kernel(
    const float* __restrict__ gb, const float* __restrict__ pb,
    const float* __restrict__ ln_w, const float* __restrict__ ln_b)
{
    const long long r = (long long)blockIdx.x * 8 + (threadIdx.x >> 5);
    const int lane = threadIdx.x & 31;
    float h[20];
    float s = 0.f, s2 = 0.f;
    #pragma unroll
    for (int j = 0; j < 20; j++) {
        const int c = lane + j * 32;
        const float gv = g_gp[r * 1280 + c] + gb[c];
        const float pv = g_gp[r * 1280 + 640 + c] + pb[c];
        const size_t ai = (size_t)r * DC + c;
        const float zse = __bfloat162float(g_ahi[ai]) + __bfloat162float(g_alo[ai]);
        const float sg = sigmoidf_(gv);
        h[j] = fmaf(sg, pv - zse, zse);
        s += h[j]; s2 += h[j] * h[j];
    }
    #pragma unroll
    for (int o = 16; o > 0; o >>= 1) {
        s  += __shfl_xor_sync(0xffffffff, s,  o);
        s2 += __shfl_xor_sync(0xffffffff, s2, o);
    }
    const float mu = s * (1.f / DC);
    const float var = fmaxf(s2 * (1.f / DC) - mu * mu, 0.f);
    const float rstd = rsqrtf(var + EPSF);
    #pragma unroll
    for (int j = 0; j < 20; j++) {
        const int c = lane + j * 32;
        const float val = (h[j] - mu) * rstd * ln_w[c] + ln_b[c];
        const __nv_bfloat16 hi = __float2bfloat16(val);
        g_ahi[r * DC + c] = hi;
        g_alo[r * DC + c] = __float2bfloat16(val - __bfloat162float(hi));
    }
}

// =====================================================================
// GroupNorm(8, 512)
// =====================================================================
__global__ void __launch_bounds__(256) gn_stats_kernel(const float* __restrict__ out)
{
    __shared__ float s1[256], s2a[256];
    const int b = blockIdx.x, g = blockIdx.y;
    float s = 0.f, s2 = 0.f;
    for (int idx = threadIdx.x; idx < TT * 64; idx += 256) {
        const int t = idx >> 6, c = idx & 63;
        const float v = out[((long long)b * TT + t) * DD + g * 64 + c];
        s += v; s2 += v * v;
    }
    s1[threadIdx.x] = s; s2a[threadIdx.x] = s2;
    __syncthreads();
    for (int o = 128; o > 0; o >>= 1) {
        if (threadIdx.x < o) { s1[threadIdx.x] += s1[threadIdx.x + o]; s2a[threadIdx.x] += s2a[threadIdx.x + o]; }
        __syncthreads();
    }
    if (threadIdx.x == 0) {
        const float inv = 1.f / (TT * 64.f);
        const float m = s1[0] * inv;
        const float var = fmaxf(s2a[0] * inv - m * m, 0.f);
        g_gn[b * 8 + g] = make_float2(m, rsqrtf(var + EPSF));
    }
}

__global__ void __launch_bounds__(256) gn_apply_kernel(
    float* __restrict__ out, const float* __restrict__ gn_w, const float* __restrict__ gn_b)
{
    const long long total4 = (long long)BT * DD / 4;
    for (long long i4 = (long long)blockIdx.x * blockDim.x + threadIdx.x;
         i4 < total4; i4 += (long long)gridDim.x * blockDim.x) {
        const long long i = i4 * 4;
        const int c = (int)(i & (DD - 1));
        const int b = (int)(i >> 20);
        const int g = c >> 6;
        const float2 mg = g_gn[b * 8 + g];
        float4 v = *(float4*)(out + i);
        v.x = (v.x - mg.x) * mg.y * gn_w[c]     + gn_b[c];
        v.y = (v.y - mg.x) * mg.y * gn_w[c + 1] + gn_b[c + 1];
        v.z = (v.z - mg.x) * mg.y * gn_w[c + 2] + gn_b[c + 2];
        v.w = (v.w - mg.x) * mg.y * gn_w[c + 3] + gn_b[c + 3];
        *(float4*)(out + i) = v;
    }
}

// =====================================================================
// launch
// =====================================================================
extern "C" void kernel_launch(void* const* d_in, const int* in_sizes, int n_in,
                              void* d_out, int out_size)
{
    const float* x    = (const float*)d_in[0];
    const float* hw1  = (const float*)d_in[1];
    const float* hb1  = (const float*)d_in[2];
    const float* hw2  = (const float*)d_in[3];
    const float* hb2  = (const float*)d_in[4];
    const float* lw1  = (const float*)d_in[5];
    const float* lb1  = (const float*)d_in[6];
    const float* lw2  = (const float*)d_in[7];
    const float* lb2  = (const float*)d_in[8];
    const float* ew1  = (const float*)d_in[9];
    const float* eb1  = (const float*)d_in[10];
    const float* ew2  = (const float*)d_in[11];
    const float* eb2  = (const float*)d_in[12];
    const float* sew1 = (const float*)d_in[13];
    const float* sew2 = (const float*)d_in[14];
    const float* gw   = (const float*)d_in[15];
    const float* gb   = (const float*)d_in[16];
    const float* pw   = (const float*)d_in[17];
    const float* pb   = (const float*)d_in[18];
    const float* lnw  = (const float*)d_in[19];
    const float* lnb  = (const float*)d_in[20];
    const float* ow   = (const float*)d_in[21];
    const float* ob   = (const float*)d_in[22];
    const float* gnw  = (const float*)d_in[23];
    const float* gnb  = (const float*)d_in[24];
    float* out = (float*)d_out;

    const int SMEM1 = (32 * CIN + 32 * DC) * 4;
    cudaFuncSetAttribute(stage1_kernel, cudaFuncAttributeMaxDynamicSharedMemorySize, SMEM1);
    cudaFuncSetAttribute(gemm_kernel,   cudaFuncAttributeMaxDynamicSharedMemorySize, GEMM_SMEM);

    prep_w_kernel<<<(WROWS * DC + 255) / 256, 256>>>(gw, pw, ow);
    stage1_kernel<<<BT / 32, 256, SMEM1>>>(x, hw1, hb1, hw2, hb2,
                                           lw1, lb1, lw2, lb2,
                                           ew1, eb1, ew2, eb2);
    se_reduce_kernel<<<dim3(BB, 5), 256>>>();
    se_mlp_kernel<<<BB, 256>>>(sew1, sew2);
    prep_a_kernel<<<8192, 256>>>();
    // gate GEMM: C = g_gp [BT,1280]
    gemm_kernel<<<dim3(10, BT / 128), 256, GEMM_SMEM>>>(0, 0, nullptr, 1280, nullptr);
    glu_ln_kernel<<<BT / 8, 256>>>(gb, pb, lnw, lnb);
    // out GEMM: C = out [BT,512] + ob
    gemm_kernel<<<dim3(4, BT / 128), 256, GEMM_SMEM>>>(1280, 1, out, DD, ob);
    gn_stats_kernel<<<dim3(BB, 8), 256>>>(out);
    gn_apply_kernel<<<4096, 256>>>(out, gnw, gnb);
}

// round 14
// speedup vs baseline: 4.3146x; 1.4963x over previous
#include <cuda_runtime.h>
#include <cuda_bf16.h>
#include <cstdint>

#define BB  64
#define TT  2048
#define BT  (BB*TT)          // 131072 rows
#define CIN 44
#define DD  512
#define DC  640
#define RED 160
#define EPSF 1e-5f
#define WROWS 1792           // 640 (gw) + 640 (pw) + 512 (ow), transposed [N][K]

// ---- scratch (device globals; no allocation allowed) ----
__device__ float  g_z[(size_t)BT * DC];              // z (zgemm output)
__device__ float  g_gp[(size_t)BT * 1280];           // raw gate/proj logits
__device__ float  g_yavg[BB * DC];
__device__ float  g_se[BB * DC];
__device__ float2 g_gn[BB * 8];
__device__ __nv_bfloat16 g_ahi[(size_t)BT * DC];     // activation split hi (hidden, then z_se, then h)
__device__ __nv_bfloat16 g_alo[(size_t)BT * DC];     // activation split lo
__device__ __nv_bfloat16 g_whi[(size_t)WROWS * DC];  // big weightsT split hi
__device__ __nv_bfloat16 g_wlo[(size_t)WROWS * DC];  // big weightsT split lo
__device__ __nv_bfloat16 g_w2hi[640 * 256];          // stage1 W2T (block-diag packed) hi
__device__ __nv_bfloat16 g_w2lo[640 * 256];          // stage1 W2T lo
__device__ float  g_sw1t[RED * DC];                  // se_w1 transposed [160][640]

extern __shared__ char smem_raw[];

__device__ __forceinline__ float sigmoidf_(float x) { return 1.f / (1.f + __expf(-x)); }

__device__ __forceinline__ uint32_t smem_u32(const void* p) {
    uint32_t a;
    asm("{ .reg .u64 t; cvta.to.shared.u64 t, %1; cvt.u32.u64 %0, t; }" : "=r"(a) : "l"(p));
    return a;
}
__device__ __forceinline__ void cp16(uint32_t s, const void* g) {
    asm volatile("cp.async.cg.shared.global [%0], [%1], 16;" :: "r"(s), "l"(g));
}
#define CP_COMMIT() asm volatile("cp.async.commit_group;" ::: "memory")
#define CP_WAIT1()  asm volatile("cp.async.wait_group 1;" ::: "memory")
#define CP_WAIT0()  asm volatile("cp.async.wait_group 0;" ::: "memory")

__device__ __forceinline__ void mma16816(float* d, const uint32_t* a, const uint32_t* b) {
    asm volatile(
        "mma.sync.aligned.m16n8k16.row.col.f32.bf16.bf16.f32 "
        "{%0,%1,%2,%3}, {%4,%5,%6,%7}, {%8,%9}, {%0,%1,%2,%3};"
        : "+f"(d[0]), "+f"(d[1]), "+f"(d[2]), "+f"(d[3])
        : "r"(a[0]), "r"(a[1]), "r"(a[2]), "r"(a[3]), "r"(b[0]), "r"(b[1]));
}

// =====================================================================
// Stage 1a: hidden = silu(x @ W1 + b1) -> bf16 hi/lo splits (g_ahi/g_alo)
// =====================================================================
__global__ void __launch_bounds__(256) stage1a_kernel(
    const float* __restrict__ x,
    const float* __restrict__ hw1, const float* __restrict__ hb1,
    const float* __restrict__ lw1, const float* __restrict__ lb1,
    const float* __restrict__ ew1, const float* __restrict__ eb1)
{
    float* xs = (float*)smem_raw;   // [32][44]
    const int tid = threadIdx.x;
    const long long r0 = (long long)blockIdx.x * 32;

    for (int i = tid; i < 32 * CIN; i += 256)
        xs[i] = x[r0 * CIN + i];
    __syncthreads();

    for (int idx = tid; idx < 32 * DC; idx += 256) {
        const int r = idx / DC, c = idx - r * DC;
        float acc;
        if (c < 256) {
            acc = hb1[c];
            #pragma unroll
            for (int k = 0; k < 14; k++) acc = fmaf(xs[r*CIN + k],      hw1[k*256 + c],  acc);
        } else if (c < 512) {
            const int cc = c - 256;
            acc = lb1[cc];
            #pragma unroll
            for (int k = 0; k < 22; k++) acc = fmaf(xs[r*CIN + 14 + k], lw1[k*256 + cc], acc);
        } else {
            const int cc = c - 512;
            acc = eb1[cc];
            #pragma unroll
            for (int k = 0; k < 8; k++)  acc = fmaf(xs[r*CIN + 36 + k], ew1[k*128 + cc], acc);
        }
        acc = acc * sigmoidf_(acc);   // silu
        const __nv_bfloat16 hi = __float2bfloat16(acc);
        const size_t gi = (r0 + r) * DC + c;
        g_ahi[gi] = hi;
        g_alo[gi] = __float2bfloat16(acc - __bfloat162float(hi));
    }
}

// =====================================================================
// zgemm: block-diagonal split-bf16 HMMA GEMM
//   z[:, nt*128 : +128] = hidden[:, koff:koff+K2] @ W2blockT + bias
//   nt 0,1 -> hw2 (koff 0, K2 256); nt 2,3 -> lw2 (koff 256, K2 256);
//   nt 4   -> ew2 (koff 512, K2 128)
// =====================================================================
#define GEMM_SMEM (2 * 36864 * 2)   // 147456 B

__global__ void __launch_bounds__(256, 1) zgemm_kernel(
    const float* __restrict__ hb2, const float* __restrict__ lb2,
    const float* __restrict__ eb2)
{
    __nv_bfloat16* sm = (__nv_bfloat16*)smem_raw;
    const int tid = threadIdx.x;
    const int lane = tid & 31, wid = tid >> 5;
    const int warp_m = wid >> 1, warp_n = wid & 1;
    const int g = lane >> 2, tg = lane & 3;
    const int nt = blockIdx.x;
    const int n0 = nt * 128;
    const int koff = (nt < 2) ? 0 : (nt < 4) ? 256 : 512;
    const int chunks = (nt < 4) ? 4 : 2;
    const long long r0 = (long long)blockIdx.y * 128;
    const float* bias = (nt < 2) ? hb2 : (nt < 4) ? lb2 : eb2;
    const int cbase = koff;

    float acc[2][8][4];
    #pragma unroll
    for (int i = 0; i < 2; i++)
        #pragma unroll
        for (int j = 0; j < 8; j++)
            #pragma unroll
            for (int v = 0; v < 4; v++) acc[i][j][v] = 0.f;

    auto loads = [&](int chunk) {
        const int st = chunk & 1;
        const int kc = chunk * 64;
        __nv_bfloat16* dst = sm + st * 36864;
        #pragma unroll
        for (int q = 0; q < 4; q++) {   // 0:Ahi 1:Alo 2:Bhi 3:Blo
            #pragma unroll
            for (int jj = 0; jj < 4; jj++) {
                const int t = tid + jj * 256;
                const int row = t >> 3, seg = t & 7;
                const void* src;
                if (q == 0)      src = g_ahi  + (r0 + row) * DC + koff + kc + seg * 8;
                else if (q == 1) src = g_alo  + (r0 + row) * DC + koff + kc + seg * 8;
                else if (q == 2) src = g_w2hi + (size_t)(n0 + row) * 256 + kc + seg * 8;
                else             src = g_w2lo + (size_t)(n0 + row) * 256 + kc + seg * 8;
                cp16(smem_u32(dst + q * 9216 + row * 72 + seg * 8), src);
            }
        }
        CP_COMMIT();
    };

    loads(0);
    for (int c = 0; c < chunks; c++) {
        if (c < chunks - 1) { loads(c + 1); CP_WAIT1(); } else { CP_WAIT0(); }
        __syncthreads();
        const __nv_bfloat16* sA  = sm + (c & 1) * 36864;
        const __nv_bfloat16* sAl = sA + 9216;
        const __nv_bfloat16* sB  = sA + 18432;
        const __nv_bfloat16* sBl = sA + 27648;
        #pragma unroll
        for (int kk = 0; kk < 64; kk += 16) {
            uint32_t ah[2][4], al[2][4], bh[8][2], bl[8][2];
            #pragma unroll
            for (int i = 0; i < 2; i++) {
                const __nv_bfloat16* p = sA  + (warp_m*32 + i*16 + g)*72 + kk + 2*tg;
                const __nv_bfloat16* q = sAl + (warp_m*32 + i*16 + g)*72 + kk + 2*tg;
                ah[i][0] = *(const uint32_t*)p;
                ah[i][1] = *(const uint32_t*)(p + 8*72);
                ah[i][2] = *(const uint32_t*)(p + 8);
                ah[i][3] = *(const uint32_t*)(p + 8*72 + 8);
                al[i][0] = *(const uint32_t*)q;
                al[i][1] = *(const uint32_t*)(q + 8*72);
                al[i][2] = *(const uint32_t*)(q + 8);
                al[i][3] = *(const uint32_t*)(q + 8*72 + 8);
            }
            #pragma unroll
            for (int j = 0; j < 8; j++) {
                const __nv_bfloat16* p = sB  + (warp_n*64 + j*8 + g)*72 + kk + 2*tg;
                const __nv_bfloat16* q = sBl + (warp_n*64 + j*8 + g)*72 + kk + 2*tg;
                bh[j][0] = *(const uint32_t*)p;
                bh[j][1] = *(const uint32_t*)(p + 8);
                bl[j][0] = *(const uint32_t*)q;
                bl[j][1] = *(const uint32_t*)(q + 8);
            }
            #pragma unroll
            for (int i = 0; i < 2; i++)
                #pragma unroll
                for (int j = 0; j < 8; j++) mma16816(acc[i][j], ah[i], bh[j]);
            #pragma unroll
            for (int i = 0; i < 2; i++)
                #pragma unroll
                for (int j = 0; j < 8; j++) mma16816(acc[i][j], ah[i], bl[j]);
            #pragma unroll
            for (int i = 0; i < 2; i++)
                #pragma unroll
                for (int j = 0; j < 8; j++) mma16816(acc[i][j], al[i], bh[j]);
        }
        __syncthreads();
    }

    #pragma unroll
    for (int i = 0; i < 2; i++) {
        const long long r = r0 + warp_m*32 + i*16 + g;
        #pragma unroll
        for (int j = 0; j < 8; j++) {
            const int cc = n0 + warp_n*64 + j*8 + 2*tg;
            const float b0 = bias[cc - cbase], b1 = bias[cc - cbase + 1];
            *(float2*)(&g_z[(size_t)r * DC + cc]) =
                make_float2(acc[i][j][0] + b0, acc[i][j][1] + b1);
            *(float2*)(&g_z[(size_t)(r + 8) * DC + cc]) =
                make_float2(acc[i][j][2] + b0, acc[i][j][3] + b1);
        }
    }
}

// =====================================================================
// SE: mean over T per (batch, channel)  +  tiny MLP
// =====================================================================
__global__ void __launch_bounds__(256) se_reduce_kernel()
{
    __shared__ float ssum[256];
    const int b = blockIdx.x;
    const int c = blockIdx.y * 128 + (threadIdx.x & 127);
    const int half = threadIdx.x >> 7;
    float s = 0.f;
    const int t0 = half * 1024;
    for (int t = t0; t < t0 + 1024; t++)
        s += g_z[((long long)b * TT + t) * DC + c];
    ssum[threadIdx.x] = s;
    __syncthreads();
    if (half == 0)
        g_yavg[b * DC + c] = (ssum[threadIdx.x] + ssum[threadIdx.x + 128]) * (1.f / TT);
}

__global__ void __launch_bounds__(256) se_mlp_kernel(
    const float* __restrict__ se_w2)
{
    __shared__ float ys[DC];
    __shared__ float hid[RED];
    const int b = blockIdx.x, tid = threadIdx.x;
    const int lane = tid & 31, wid = tid >> 5;
    for (int c = tid; c < DC; c += 256) ys[c] = g_yavg[b * DC + c];
    __syncthreads();
    // phase 1: warp per output, coalesced rows of se_w1T
    for (int o = wid; o < RED; o += 8) {
        float acc = 0.f;
        #pragma unroll
        for (int kk = 0; kk < 20; kk++) {
            const int k = lane + kk * 32;
            acc = fmaf(ys[k], g_sw1t[o * DC + k], acc);
        }
        #pragma unroll
        for (int off = 16; off > 0; off >>= 1)
            acc += __shfl_xor_sync(0xffffffff, acc, off);
        if (lane == 0) hid[o] = fmaxf(acc, 0.f);
    }
    __syncthreads();
    for (int c = tid; c < DC; c += 256) {
        float acc = 0.f;
        for (int j = 0; j < RED; j++) acc = fmaf(hid[j], se_w2[j * DC + c], acc);
        g_se[b * DC + c] = sigmoidf_(acc);
    }
}

// =====================================================================
// prep_w: transpose + bf16-split big weights into combined [1792][640]
// =====================================================================
__global__ void __launch_bounds__(256) prep_w_kernel(
    const float* __restrict__ gw, const float* __restrict__ pw, const float* __restrict__ ow)
{
    const int idx = blockIdx.x * 256 + threadIdx.x;
    if (idx >= WROWS * DC) return;
    const int n = idx / DC, k = idx - n * DC;
    float v;
    if (n < 640)       v = gw[(size_t)k * DC + n];
    else if (n < 1280) v = pw[(size_t)k * DC + (n - 640)];
    else               v = ow[(size_t)k * DD + (n - 1280)];
    const __nv_bfloat16 hi = __float2bfloat16(v);
    g_whi[idx] = hi;
    g_wlo[idx] = __float2bfloat16(v - __bfloat162float(hi));
}

// =====================================================================
// prep_aux: pack stage1 W2T (block-diag, [640][256]) splits + se_w1T
// =====================================================================
__global__ void __launch_bounds__(256) prep_aux_kernel(
    const float* __restrict__ hw2, const float* __restrict__ lw2,
    const float* __restrict__ ew2, const float* __restrict__ se_w1)
{
    const int idx = blockIdx.x * 256 + threadIdx.x;
    if (idx < 640 * 256) {
        const int n = idx >> 8, k = idx & 255;
        float v;
        if (n < 256)      v = hw2[k * 256 + n];
        else if (n < 512) v = lw2[k * 256 + (n - 256)];
        else              v = (k < 128) ? ew2[k * 128 + (n - 512)] : 0.f;
        const __nv_bfloat16 hi = __float2bfloat16(v);
        g_w2hi[idx] = hi;
        g_w2lo[idx] = __float2bfloat16(v - __bfloat162float(hi));
    } else if (idx < 640 * 256 + RED * DC) {
        const int i = idx - 640 * 256;
        const int o = i / DC, k = i - o * DC;
        g_sw1t[i] = se_w1[k * RED + o];
    }
}

// =====================================================================
// prep_a: z_se = z * se  -> bf16 hi/lo split
// =====================================================================
__global__ void __launch_bounds__(256) prep_a_kernel()
{
    const size_t total4 = (size_t)BT * DC / 4;
    for (size_t i4 = (size_t)blockIdx.x * 256 + threadIdx.x; i4 < total4;
         i4 += (size_t)gridDim.x * 256) {
        const size_t i = i4 * 4;
        const int r = (int)(i / DC);
        const int b = r >> 11;
        const int c = (int)(i - (size_t)r * DC);
        const float4 v = *(const float4*)(g_z + i);
        const float* se = g_se + b * DC + c;
        const float z0 = v.x * se[0], z1 = v.y * se[1], z2 = v.z * se[2], z3 = v.w * se[3];
        const __nv_bfloat16 h0 = __float2bfloat16(z0), h1 = __float2bfloat16(z1);
        const __nv_bfloat16 h2 = __float2bfloat16(z2), h3 = __float2bfloat16(z3);
        __nv_bfloat162* ph = (__nv_bfloat162*)(g_ahi + i);
        ph[0] = __halves2bfloat162(h0, h1);
        ph[1] = __halves2bfloat162(h2, h3);
        __nv_bfloat162* pl = (__nv_bfloat162*)(g_alo + i);
        pl[0] = __halves2bfloat162(__float2bfloat16(z0 - __bfloat162float(h0)),
                                   __float2bfloat16(z1 - __bfloat162float(h1)));
        pl[1] = __halves2bfloat162(__float2bfloat16(z2 - __bfloat162float(h2)),
                                   __float2bfloat16(z3 - __bfloat162float(h3)));
    }
}

// =====================================================================
// Generic split-bf16 HMMA GEMM (validated R11):
//   C[r0:r0+128, n0:n0+128] = A[r,:640] @ W[wrow0+n, :640]^T (+bias)
// =====================================================================
__global__ void __launch_bounds__(256, 1) gemm_kernel(
    int wrow0, int which, float* __restrict__ Cext, int ldc,
    const float* __restrict__ bias)
{
    __nv_bfloat16* sm = (__nv_bfloat16*)smem_raw;
    const int tid = threadIdx.x;
    const int lane = tid & 31, wid = tid >> 5;
    const int warp_m = wid >> 1, warp_n = wid & 1;
    const int g = lane >> 2, tg = lane & 3;
    const int n0 = blockIdx.x * 128;
    const long long r0 = (long long)blockIdx.y * 128;
    float* __restrict__ C = which ? Cext : g_gp;

    float acc[2][8][4];
    #pragma unroll
    for (int i = 0; i < 2; i++)
        #pragma unroll
        for (int j = 0; j < 8; j++)
            #pragma unroll
            for (int v = 0; v < 4; v++) acc[i][j][v] = 0.f;

    auto loads = [&](int chunk) {
        const int st = chunk & 1;
        const int kc = chunk * 64;
        __nv_bfloat16* dst = sm + st * 36864;
        #pragma unroll
        for (int q = 0; q < 4; q++) {   // 0:Ahi 1:Alo 2:Bhi 3:Blo
            const __nv_bfloat16* src = (q == 0) ? g_ahi : (q == 1) ? g_alo
                                     : (q == 2) ? g_whi : g_wlo;
            const long long rowbase = (q < 2) ? r0 : (long long)(wrow0 + n0);
            #pragma unroll
            for (int jj = 0; jj < 4; jj++) {
                const int t = tid + jj * 256;
                const int row = t >> 3, seg = t & 7;
                cp16(smem_u32(dst + q * 9216 + row * 72 + seg * 8),
                     src + (rowbase + row) * DC + kc + seg * 8);
            }
        }
        CP_COMMIT();
    };

    loads(0);
    for (int c = 0; c < 10; c++) {
        if (c < 9) { loads(c + 1); CP_WAIT1(); } else { CP_WAIT0(); }
        __syncthreads();
        const __nv_bfloat16* sA  = sm + (c & 1) * 36864;
        const __nv_bfloat16* sAl = sA + 9216;
        const __nv_bfloat16* sB  = sA + 18432;
        const __nv_bfloat16* sBl = sA + 27648;
        #pragma unroll
        for (int kk = 0; kk < 64; kk += 16) {
            uint32_t ah[2][4], al[2][4], bh[8][2], bl[8][2];
            #pragma unroll
            for (int i = 0; i < 2; i++) {
                const __nv_bfloat16* p = sA  + (warp_m*32 + i*16 + g)*72 + kk + 2*tg;
                const __nv_bfloat16* q = sAl + (warp_m*32 + i*16 + g)*72 + kk + 2*tg;
                ah[i][0] = *(const uint32_t*)p;
                ah[i][1] = *(const uint32_t*)(p + 8*72);
                ah[i][2] = *(const uint32_t*)(p + 8);
                ah[i][3] = *(const uint32_t*)(p + 8*72 + 8);
                al[i][0] = *(const uint32_t*)q;
                al[i][1] = *(const uint32_t*)(q + 8*72);
                al[i][2] = *(const uint32_t*)(q + 8);
                al[i][3] = *(const uint32_t*)(q + 8*72 + 8);
            }
            #pragma unroll
            for (int j = 0; j < 8; j++) {
                const __nv_bfloat16* p = sB  + (warp_n*64 + j*8 + g)*72 + kk + 2*tg;
                const __nv_bfloat16* q = sBl + (warp_n*64 + j*8 + g)*72 + kk + 2*tg;
                bh[j][0] = *(const uint32_t*)p;
                bh[j][1] = *(const uint32_t*)(p + 8);
                bl[j][0] = *(const uint32_t*)q;
                bl[j][1] = *(const uint32_t*)(q + 8);
            }
            #pragma unroll
            for (int i = 0; i < 2; i++)
                #pragma unroll
                for (int j = 0; j < 8; j++) mma16816(acc[i][j], ah[i], bh[j]);
            #pragma unroll
            for (int i = 0; i < 2; i++)
                #pragma unroll
                for (int j = 0; j < 8; j++) mma16816(acc[i][j], ah[i], bl[j]);
            #pragma unroll
            for (int i = 0; i < 2; i++)
                #pragma unroll
                for (int j = 0; j < 8; j++) mma16816(acc[i][j], al[i], bh[j]);
        }
        __syncthreads();
    }

    #pragma unroll
    for (int i = 0; i < 2; i++) {
        const long long r = r0 + warp_m*32 + i*16 + g;
        #pragma unroll
        for (int j = 0; j < 8; j++) {
            const int cc = n0 + warp_n*64 + j*8 + 2*tg;
            float b0 = 0.f, b1 = 0.f;
            if (which) { b0 = bias[cc]; b1 = bias[cc + 1]; }
            *(float2*)(&C[(size_t)r * ldc + cc]) =
                make_float2(acc[i][j][0] + b0, acc[i][j][1] + b1);
            *(float2*)(&C[(size_t)(r + 8) * ldc + cc]) =
                make_float2(acc[i][j][2] + b0, acc[i][j][3] + b1);
        }
    }
}

// =====================================================================
// GLU + LayerNorm fused (warp per row)
// =====================================================================
__global__ void __launch_bounds__(256) glu_ln_kernel(
    const float* __restrict__ gb, const float* __restrict__ pb,
    const float* __restrict__ ln_w, const float* __restrict__ ln_b)
{
    const long long r = (long long)blockIdx.x * 8 + (threadIdx.x >> 5);
    const int lane = threadIdx.x & 31;
    float h[20];
    float s = 0.f, s2 = 0.f;
    #pragma unroll
    for (int j = 0; j < 20; j++) {
        const int c = lane + j * 32;
        const float gv = g_gp[r * 1280 + c] + gb[c];
        const float pv = g_gp[r * 1280 + 640 + c] + pb[c];
        const size_t ai = (size_t)r * DC + c;
        const float zse = __bfloat162float(g_ahi[ai]) + __bfloat162float(g_alo[ai]);
        const float sg = sigmoidf_(gv);
        h[j] = fmaf(sg, pv - zse, zse);
        s += h[j]; s2 += h[j] * h[j];
    }
    #pragma unroll
    for (int o = 16; o > 0; o >>= 1) {
        s  += __shfl_xor_sync(0xffffffff, s,  o);
        s2 += __shfl_xor_sync(0xffffffff, s2, o);
    }
    const float mu = s * (1.f / DC);
    const float var = fmaxf(s2 * (1.f / DC) - mu * mu, 0.f);
    const float rstd = rsqrtf(var + EPSF);
    #pragma unroll
    for (int j = 0; j < 20; j++) {
        const int c = lane + j * 32;
        const float val = (h[j] - mu) * rstd * ln_w[c] + ln_b[c];
        const __nv_bfloat16 hi = __float2bfloat16(val);
        g_ahi[r * DC + c] = hi;
        g_alo[r * DC + c] = __float2bfloat16(val - __bfloat162float(hi));
    }
}

// =====================================================================
// GroupNorm(8, 512)
// =====================================================================
__global__ void __launch_bounds__(256) gn_stats_kernel(const float* __restrict__ out)
{
    __shared__ float s1[256], s2a[256];
    const int b = blockIdx.x, g = blockIdx.y;
    float s = 0.f, s2 = 0.f;
    for (int idx = threadIdx.x; idx < TT * 64; idx += 256) {
        const int t = idx >> 6, c = idx & 63;
        const float v = out[((long long)b * TT + t) * DD + g * 64 + c];
        s += v; s2 += v * v;
    }
    s1[threadIdx.x] = s; s2a[threadIdx.x] = s2;
    __syncthreads();
    for (int o = 128; o > 0; o >>= 1) {
        if (threadIdx.x < o) { s1[threadIdx.x] += s1[threadIdx.x + o]; s2a[threadIdx.x] += s2a[threadIdx.x + o]; }
        __syncthreads();
    }
    if (threadIdx.x == 0) {
        const float inv = 1.f / (TT * 64.f);
        const float m = s1[0] * inv;
        const float var = fmaxf(s2a[0] * inv - m * m, 0.f);
        g_gn[b * 8 + g] = make_float2(m, rsqrtf(var + EPSF));
    }
}

__global__ void __launch_bounds__(256) gn_apply_kernel(
    float* __restrict__ out, const float* __restrict__ gn_w, const float* __restrict__ gn_b)
{
    const long long total4 = (long long)BT * DD / 4;
    for (long long i4 = (long long)blockIdx.x * blockDim.x + threadIdx.x;
         i4 < total4; i4 += (long long)gridDim.x * blockDim.x) {
        const long long i = i4 * 4;
        const int c = (int)(i & (DD - 1));
        const int b = (int)(i >> 20);
        const int g = c >> 6;
        const float2 mg = g_gn[b * 8 + g];
        float4 v = *(float4*)(out + i);
        v.x = (v.x - mg.x) * mg.y * gn_w[c]     + gn_b[c];
        v.y = (v.y - mg.x) * mg.y * gn_w[c + 1] + gn_b[c + 1];
        v.z = (v.z - mg.x) * mg.y * gn_w[c + 2] + gn_b[c + 2];
        v.w = (v.w - mg.x) * mg.y * gn_w[c + 3] + gn_b[c + 3];
        *(float4*)(out + i) = v;
    }
}

// =====================================================================
// launch
// =====================================================================
extern "C" void kernel_launch(void* const* d_in, const int* in_sizes, int n_in,
                              void* d_out, int out_size)
{
    const float* x    = (const float*)d_in[0];
    const float* hw1  = (const float*)d_in[1];
    const float* hb1  = (const float*)d_in[2];
    const float* hw2  = (const float*)d_in[3];
    const float* hb2  = (const float*)d_in[4];
    const float* lw1  = (const float*)d_in[5];
    const float* lb1  = (const float*)d_in[6];
    const float* lw2  = (const float*)d_in[7];
    const float* lb2  = (const float*)d_in[8];
    const float* ew1  = (const float*)d_in[9];
    const float* eb1  = (const float*)d_in[10];
    const float* ew2  = (const float*)d_in[11];
    const float* eb2  = (const float*)d_in[12];
    const float* sew1 = (const float*)d_in[13];
    const float* sew2 = (const float*)d_in[14];
    const float* gw   = (const float*)d_in[15];
    const float* gb   = (const float*)d_in[16];
    const float* pw   = (const float*)d_in[17];
    const float* pb   = (const float*)d_in[18];
    const float* lnw  = (const float*)d_in[19];
    const float* lnb  = (const float*)d_in[20];
    const float* ow   = (const float*)d_in[21];
    const float* ob   = (const float*)d_in[22];
    const float* gnw  = (const float*)d_in[23];
    const float* gnb  = (const float*)d_in[24];
    float* out = (float*)d_out;

    const int SMEM1A = 32 * CIN * 4;
    cudaFuncSetAttribute(stage1a_kernel, cudaFuncAttributeMaxDynamicSharedMemorySize, SMEM1A);
    cudaFuncSetAttribute(zgemm_kernel,   cudaFuncAttributeMaxDynamicSharedMemorySize, GEMM_SMEM);
    cudaFuncSetAttribute(gemm_kernel,    cudaFuncAttributeMaxDynamicSharedMemorySize, GEMM_SMEM);

    prep_w_kernel<<<(WROWS * DC + 255) / 256, 256>>>(gw, pw, ow);
    prep_aux_kernel<<<(640 * 256 + RED * DC + 255) / 256, 256>>>(hw2, lw2, ew2, sew1);
    stage1a_kernel<<<BT / 32, 256, SMEM1A>>>(x, hw1, hb1, lw1, lb1, ew1, eb1);
    zgemm_kernel<<<dim3(5, BT / 128), 256, GEMM_SMEM>>>(hb2, lb2, eb2);
    se_reduce_kernel<<<dim3(BB, 5), 256>>>();
    se_mlp_kernel<<<BB, 256>>>(sew2);
    prep_a_kernel<<<8192, 256>>>();
    // gate GEMM: C = g_gp [BT,1280]
    gemm_kernel<<<dim3(10, BT / 128), 256, GEMM_SMEM>>>(0, 0, nullptr, 1280, nullptr);
    glu_ln_kernel<<<BT / 8, 256>>>(gb, pb, lnw, lnb);
    // out GEMM: C = out [BT,512] + ob
    gemm_kernel<<<dim3(4, BT / 128), 256, GEMM_SMEM>>>(1280, 1, out, DD, ob);
    gn_stats_kernel<<<dim3(BB, 8), 256>>>(out);
    gn_apply_kernel<<<4096, 256>>>(out, gnw, gnb);
}

// round 16
// speedup vs baseline: 4.4734x; 1.0368x over previous
#include <cuda_runtime.h>
#include <cuda_bf16.h>
#include <cstdint>

#define BB  64
#define TT  2048
#define BT  (BB*TT)          // 131072 rows
#define CIN 44
#define DD  512
#define DC  640
#define RED 160
#define EPSF 1e-5f
#define WROWS 1792           // 640 (gw) + 640 (pw) + 512 (ow), transposed [N][K]

// ---- scratch (device globals; no allocation allowed) ----
__device__ float  g_z[(size_t)BT * DC];              // z (zgemm output)
__device__ float  g_gp[(size_t)BT * 1280];           // raw gate/proj logits
__device__ float  g_yavg[BB * DC];                   // column sums of z (atomic)
__device__ float  g_se[BB * DC];
__device__ float  g_gnsum[BB * 8 * 2];               // GN sums (atomic): [b][grp][0]=s,[1]=s2
__device__ float2 g_gn[BB * 8];
__device__ __nv_bfloat16 g_ahi[(size_t)BT * DC];     // activation split hi
__device__ __nv_bfloat16 g_alo[(size_t)BT * DC];     // activation split lo
__device__ __nv_bfloat16 g_whi[(size_t)WROWS * DC];  // big weightsT split hi
__device__ __nv_bfloat16 g_wlo[(size_t)WROWS * DC];  // big weightsT split lo
__device__ __nv_bfloat16 g_w2hi[640 * 256];          // stage1 W2T (block-diag packed) hi
__device__ __nv_bfloat16 g_w2lo[640 * 256];          // stage1 W2T lo
__device__ float  g_sw1t[RED * DC];                  // se_w1 transposed [160][640]

extern __shared__ char smem_raw[];

__device__ __forceinline__ float sigmoidf_(float x) { return 1.f / (1.f + __expf(-x)); }

__device__ __forceinline__ uint32_t smem_u32(const void* p) {
    uint32_t a;
    asm("{ .reg .u64 t; cvta.to.shared.u64 t, %1; cvt.u32.u64 %0, t; }" : "=r"(a) : "l"(p));
    return a;
}
__device__ __forceinline__ void cp16(uint32_t s, const void* g) {
    asm volatile("cp.async.cg.shared.global [%0], [%1], 16;" :: "r"(s), "l"(g));
}
#define CP_COMMIT() asm volatile("cp.async.commit_group;" ::: "memory")
#define CP_WAIT1()  asm volatile("cp.async.wait_group 1;" ::: "memory")
#define CP_WAIT0()  asm volatile("cp.async.wait_group 0;" ::: "memory")

__device__ __forceinline__ void mma16816(float* d, const uint32_t* a, const uint32_t* b) {
    asm volatile(
        "mma.sync.aligned.m16n8k16.row.col.f32.bf16.bf16.f32 "
        "{%0,%1,%2,%3}, {%4,%5,%6,%7}, {%8,%9}, {%0,%1,%2,%3};"
        : "+f"(d[0]), "+f"(d[1]), "+f"(d[2]), "+f"(d[3])
        : "r"(a[0]), "r"(a[1]), "r"(a[2]), "r"(a[3]), "r"(b[0]), "r"(b[1]));
}

// SMEM geometry: K-chunk 32, rows padded to 40 halves (80 B).
// Quadrant = 128 rows * 40 halves = 5120 halves; stage = 4 quadrants = 20480 halves (40960 B).
#define GEMM_SMEM (2 * 20480 * 2)   // 81920 B -> 2 CTAs/SM

// =====================================================================
// zero accumulators (every call; graph node)
// =====================================================================
__global__ void __launch_bounds__(256) zero_kernel()
{
    const int i = blockIdx.x * 256 + threadIdx.x;
    if (i < BB * DC) g_yavg[i] = 0.f;
    if (i < BB * 8 * 2) g_gnsum[i] = 0.f;
}

// =====================================================================
// Stage 1a: hidden = silu(x @ W1 + b1) -> bf16 hi/lo splits
// =====================================================================
__global__ void __launch_bounds__(256) stage1a_kernel(
    const float* __restrict__ x,
    const float* __restrict__ hw1, const float* __restrict__ hb1,
    const float* __restrict__ lw1, const float* __restrict__ lb1,
    const float* __restrict__ ew1, const float* __restrict__ eb1)
{
    float* xs = (float*)smem_raw;   // [32][44]
    const int tid = threadIdx.x;
    const long long r0 = (long long)blockIdx.x * 32;

    for (int i = tid; i < 32 * CIN; i += 256)
        xs[i] = x[r0 * CIN + i];
    __syncthreads();

    for (int idx = tid; idx < 32 * DC; idx += 256) {
        const int r = idx / DC, c = idx - r * DC;
        float acc;
        if (c < 256) {
            acc = hb1[c];
            #pragma unroll
            for (int k = 0; k < 14; k++) acc = fmaf(xs[r*CIN + k],      hw1[k*256 + c],  acc);
        } else if (c < 512) {
            const int cc = c - 256;
            acc = lb1[cc];
            #pragma unroll
            for (int k = 0; k < 22; k++) acc = fmaf(xs[r*CIN + 14 + k], lw1[k*256 + cc], acc);
        } else {
            const int cc = c - 512;
            acc = eb1[cc];
            #pragma unroll
            for (int k = 0; k < 8; k++)  acc = fmaf(xs[r*CIN + 36 + k], ew1[k*128 + cc], acc);
        }
        acc = acc * sigmoidf_(acc);   // silu
        const __nv_bfloat16 hi = __float2bfloat16(acc);
        const size_t gi = (r0 + r) * DC + c;
        g_ahi[gi] = hi;
        g_alo[gi] = __float2bfloat16(acc - __bfloat162float(hi));
    }
}

// =====================================================================
// zgemm: block-diagonal split-bf16 HMMA GEMM + fused column-sum (SE pool)
// =====================================================================
__global__ void __launch_bounds__(256, 2) zgemm_kernel(
    const float* __restrict__ hb2, const float* __restrict__ lb2,
    const float* __restrict__ eb2)
{
    __nv_bfloat16* sm = (__nv_bfloat16*)smem_raw;
    const int tid = threadIdx.x;
    const int lane = tid & 31, wid = tid >> 5;
    const int warp_m = wid >> 1, warp_n = wid & 1;
    const int g = lane >> 2, tg = lane & 3;
    const int nt = blockIdx.x;
    const int n0 = nt * 128;
    const int koff = (nt < 2) ? 0 : (nt < 4) ? 256 : 512;
    const int chunks = (nt < 4) ? 8 : 4;
    const long long r0 = (long long)blockIdx.y * 128;
    const int b = (int)(blockIdx.y >> 4);            // 2048/128 = 16 M-blocks per batch
    const float* bias = (nt < 2) ? hb2 : (nt < 4) ? lb2 : eb2;
    const int cbase = koff;

    float acc[2][8][4];
    #pragma unroll
    for (int i = 0; i < 2; i++)
        #pragma unroll
        for (int j = 0; j < 8; j++)
            #pragma unroll
            for (int v = 0; v < 4; v++) acc[i][j][v] = 0.f;

    auto loads = [&](int chunk) {
        const int st = chunk & 1;
        const int kc = chunk * 32;
        __nv_bfloat16* dst = sm + st * 20480;
        #pragma unroll
        for (int q = 0; q < 4; q++) {
            #pragma unroll
            for (int it = 0; it < 2; it++) {
                const int t = tid + it * 256;
                const int row = t >> 2, seg = t & 3;
                const void* src;
                if (q == 0)      src = g_ahi  + (r0 + row) * DC + koff + kc + seg * 8;
                else if (q == 1) src = g_alo  + (r0 + row) * DC + koff + kc + seg * 8;
                else if (q == 2) src = g_w2hi + (size_t)(n0 + row) * 256 + kc + seg * 8;
                else             src = g_w2lo + (size_t)(n0 + row) * 256 + kc + seg * 8;
                cp16(smem_u32(dst + q * 5120 + row * 40 + seg * 8), src);
            }
        }
        CP_COMMIT();
    };

    loads(0);
    for (int c = 0; c < chunks; c++) {
        if (c < chunks - 1) { loads(c + 1); CP_WAIT1(); } else { CP_WAIT0(); }
        __syncthreads();
        const __nv_bfloat16* sA  = sm + (c & 1) * 20480;
        const __nv_bfloat16* sAl = sA + 5120;
        const __nv_bfloat16* sB  = sA + 10240;
        const __nv_bfloat16* sBl = sA + 15360;
        #pragma unroll
        for (int kk = 0; kk < 32; kk += 16) {
            uint32_t ah[2][4], al[2][4];
            #pragma unroll
            for (int i = 0; i < 2; i++) {
                const __nv_bfloat16* p = sA  + (warp_m*32 + i*16 + g)*40 + kk + 2*tg;
                const __nv_bfloat16* q = sAl + (warp_m*32 + i*16 + g)*40 + kk + 2*tg;
                ah[i][0] = *(const uint32_t*)p;
                ah[i][1] = *(const uint32_t*)(p + 8*40);
                ah[i][2] = *(const uint32_t*)(p + 8);
                ah[i][3] = *(const uint32_t*)(p + 8*40 + 8);
                al[i][0] = *(const uint32_t*)q;
                al[i][1] = *(const uint32_t*)(q + 8*40);
                al[i][2] = *(const uint32_t*)(q + 8);
                al[i][3] = *(const uint32_t*)(q + 8*40 + 8);
            }
            #pragma unroll
            for (int j = 0; j < 8; j++) {
                const __nv_bfloat16* p = sB  + (warp_n*64 + j*8 + g)*40 + kk + 2*tg;
                const __nv_bfloat16* q = sBl + (warp_n*64 + j*8 + g)*40 + kk + 2*tg;
                uint32_t bh[2], bl[2];
                bh[0] = *(const uint32_t*)p;
                bh[1] = *(const uint32_t*)(p + 8);
                bl[0] = *(const uint32_t*)q;
                bl[1] = *(const uint32_t*)(q + 8);
                mma16816(acc[0][j], ah[0], bh);
                mma16816(acc[1][j], ah[1], bh);
                mma16816(acc[0][j], ah[0], bl);
                mma16816(acc[1][j], ah[1], bl);
                mma16816(acc[0][j], al[0], bh);
                mma16816(acc[1][j], al[1], bh);
            }
        }
        __syncthreads();
    }

    // epilogue: write z (+bias) and accumulate column sums for SE pooling
    float* scol = (float*)smem_raw;   // reuse (all warps past final sync)
    if (tid < 128) scol[tid] = 0.f;
    __syncthreads();
    #pragma unroll
    for (int j = 0; j < 8; j++) {
        const int ccl = warp_n*64 + j*8 + 2*tg;
        const int cc = n0 + ccl;
        const float b0 = bias[cc - cbase], b1 = bias[cc - cbase + 1];
        float c0 = 4.f * b0, c1 = 4.f * b1;
        #pragma unroll
        for (int i = 0; i < 2; i++) {
            const long long r = r0 + warp_m*32 + i*16 + g;
            *(float2*)(&g_z[(size_t)r * DC + cc]) =
                make_float2(acc[i][j][0] + b0, acc[i][j][1] + b1);
            *(float2*)(&g_z[(size_t)(r + 8) * DC + cc]) =
                make_float2(acc[i][j][2] + b0, acc[i][j][3] + b1);
            c0 += acc[i][j][0] + acc[i][j][2];
            c1 += acc[i][j][1] + acc[i][j][3];
        }
        #pragma unroll
        for (int off = 16; off >= 4; off >>= 1) {
            c0 += __shfl_xor_sync(0xffffffff, c0, off);
            c1 += __shfl_xor_sync(0xffffffff, c1, off);
        }
        if (lane < 4) {            // g == 0
            atomicAdd(&scol[ccl],     c0);
            atomicAdd(&scol[ccl + 1], c1);
        }
    }
    __syncthreads();
    if (tid < 128) atomicAdd(&g_yavg[b * DC + n0 + tid], scol[tid]);
}

// =====================================================================
// SE MLP (reads raw column sums; scales by 1/TT)
// =====================================================================
__global__ void __launch_bounds__(256) se_mlp_kernel(
    const float* __restrict__ se_w2)
{
    __shared__ float ys[DC];
    __shared__ float hid[RED];
    const int b = blockIdx.x, tid = threadIdx.x;
    const int lane = tid & 31, wid = tid >> 5;
    for (int c = tid; c < DC; c += 256) ys[c] = g_yavg[b * DC + c] * (1.f / TT);
    __syncthreads();
    for (int o = wid; o < RED; o += 8) {
        float acc = 0.f;
        #pragma unroll
        for (int kk = 0; kk < 20; kk++) {
            const int k = lane + kk * 32;
            acc = fmaf(ys[k], g_sw1t[o * DC + k], acc);
        }
        #pragma unroll
        for (int off = 16; off > 0; off >>= 1)
            acc += __shfl_xor_sync(0xffffffff, acc, off);
        if (lane == 0) hid[o] = fmaxf(acc, 0.f);
    }
    __syncthreads();
    for (int c = tid; c < DC; c += 256) {
        float acc = 0.f;
        for (int j = 0; j < RED; j++) acc = fmaf(hid[j], se_w2[j * DC + c], acc);
        g_se[b * DC + c] = sigmoidf_(acc);
    }
}

// =====================================================================
// prep_w: transpose + bf16-split big weights into combined [1792][640]
// =====================================================================
__global__ void __launch_bounds__(256) prep_w_kernel(
    const float* __restrict__ gw, const float* __restrict__ pw, const float* __restrict__ ow)
{
    const int idx = blockIdx.x * 256 + threadIdx.x;
    if (idx >= WROWS * DC) return;
    const int n = idx / DC, k = idx - n * DC;
    float v;
    if (n < 640)       v = gw[(size_t)k * DC + n];
    else if (n < 1280) v = pw[(size_t)k * DC + (n - 640)];
    else               v = ow[(size_t)k * DD + (n - 1280)];
    const __nv_bfloat16 hi = __float2bfloat16(v);
    g_whi[idx] = hi;
    g_wlo[idx] = __float2bfloat16(v - __bfloat162float(hi));
}

// =====================================================================
// prep_aux: pack stage1 W2T (block-diag, [640][256]) splits + se_w1T
// =====================================================================
__global__ void __launch_bounds__(256) prep_aux_kernel(
    const float* __restrict__ hw2, const float* __restrict__ lw2,
    const float* __restrict__ ew2, const float* __restrict__ se_w1)
{
    const int idx = blockIdx.x * 256 + threadIdx.x;
    if (idx < 640 * 256) {
        const int n = idx >> 8, k = idx & 255;
        float v;
        if (n < 256)      v = hw2[k * 256 + n];
        else if (n < 512) v = lw2[k * 256 + (n - 256)];
        else              v = (k < 128) ? ew2[k * 128 + (n - 512)] : 0.f;
        const __nv_bfloat16 hi = __float2bfloat16(v);
        g_w2hi[idx] = hi;
        g_w2lo[idx] = __float2bfloat16(v - __bfloat162float(hi));
    } else if (idx < 640 * 256 + RED * DC) {
        const int i = idx - 640 * 256;
        const int o = i / DC, k = i - o * DC;
        g_sw1t[i] = se_w1[k * RED + o];
    }
}

// =====================================================================
// prep_a: z_se = z * se  -> bf16 hi/lo split
// =====================================================================
__global__ void __launch_bounds__(256) prep_a_kernel()
{
    const size_t total4 = (size_t)BT * DC / 4;
    for (size_t i4 = (size_t)blockIdx.x * 256 + threadIdx.x; i4 < total4;
         i4 += (size_t)gridDim.x * 256) {
        const size_t i = i4 * 4;
        const int r = (int)(i / DC);
        const int b = r >> 11;
        const int c = (int)(i - (size_t)r * DC);
        const float4 v = *(const float4*)(g_z + i);
        const float* se = g_se + b * DC + c;
        const float z0 = v.x * se[0], z1 = v.y * se[1], z2 = v.z * se[2], z3 = v.w * se[3];
        const __nv_bfloat16 h0 = __float2bfloat16(z0), h1 = __float2bfloat16(z1);
        const __nv_bfloat16 h2 = __float2bfloat16(z2), h3 = __float2bfloat16(z3);
        __nv_bfloat162* ph = (__nv_bfloat162*)(g_ahi + i);
        ph[0] = __halves2bfloat162(h0, h1);
        ph[1] = __halves2bfloat162(h2, h3);
        __nv_bfloat162* pl = (__nv_bfloat162*)(g_alo + i);
        pl[0] = __halves2bfloat162(__float2bfloat16(z0 - __bfloat162float(h0)),
                                   __float2bfloat16(z1 - __bfloat162float(h1)));
        pl[1] = __halves2bfloat162(__float2bfloat16(z2 - __bfloat162float(h2)),
                                   __float2bfloat16(z3 - __bfloat162float(h3)));
    }
}

// =====================================================================
// Generic split-bf16 HMMA GEMM (2 CTAs/SM):
//   C[r0:r0+128, n0:n0+128] = A[r,:640] @ W[wrow0+n, :640]^T (+bias)
//   which=1 (out GEMM) also accumulates GroupNorm sum/sumsq atomically.
// =====================================================================
__global__ void __launch_bounds__(256, 2) gemm_kernel(
    int wrow0, int which, float* __restrict__ Cext, int ldc,
    const float* __restrict__ bias)
{
    __nv_bfloat16* sm = (__nv_bfloat16*)smem_raw;
    const int tid = threadIdx.x;
    const int lane = tid & 31, wid = tid >> 5;
    const int warp_m = wid >> 1, warp_n = wid & 1;
    const int g = lane >> 2, tg = lane & 3;
    const int n0 = blockIdx.x * 128;
    const long long r0 = (long long)blockIdx.y * 128;
    float* __restrict__ C = which ? Cext : g_gp;

    float acc[2][8][4];
    #pragma unroll
    for (int i = 0; i < 2; i++)
        #pragma unroll
        for (int j = 0; j < 8; j++)
            #pragma unroll
            for (int v = 0; v < 4; v++) acc[i][j][v] = 0.f;

    auto loads = [&](int chunk) {
        const int st = chunk & 1;
        const int kc = chunk * 32;
        __nv_bfloat16* dst = sm + st * 20480;
        #pragma unroll
        for (int q = 0; q < 4; q++) {
            const __nv_bfloat16* src = (q == 0) ? g_ahi : (q == 1) ? g_alo
                                     : (q == 2) ? g_whi : g_wlo;
            const long long rowbase = (q < 2) ? r0 : (long long)(wrow0 + n0);
            #pragma unroll
            for (int it = 0; it < 2; it++) {
                const int t = tid + it * 256;
                const int row = t >> 2, seg = t & 3;
                cp16(smem_u32(dst + q * 5120 + row * 40 + seg * 8),
                     src + (rowbase + row) * DC + kc + seg * 8);
            }
        }
        CP_COMMIT();
    };

    loads(0);
    for (int c = 0; c < 20; c++) {
        if (c < 19) { loads(c + 1); CP_WAIT1(); } else { CP_WAIT0(); }
        __syncthreads();
        const __nv_bfloat16* sA  = sm + (c & 1) * 20480;
        const __nv_bfloat16* sAl = sA + 5120;
        const __nv_bfloat16* sB  = sA + 10240;
        const __nv_bfloat16* sBl = sA + 15360;
        #pragma unroll
        for (int kk = 0; kk < 32; kk += 16) {
            uint32_t ah[2][4], al[2][4];
            #pragma unroll
            for (int i = 0; i < 2; i++) {
                const __nv_bfloat16* p = sA  + (warp_m*32 + i*16 + g)*40 + kk + 2*tg;
                const __nv_bfloat16* q = sAl + (warp_m*32 + i*16 + g)*40 + kk + 2*tg;
                ah[i][0] = *(const uint32_t*)p;
                ah[i][1] = *(const uint32_t*)(p + 8*40);
                ah[i][2] = *(const uint32_t*)(p + 8);
                ah[i][3] = *(const uint32_t*)(p + 8*40 + 8);
                al[i][0] = *(const uint32_t*)q;
                al[i][1] = *(const uint32_t*)(q + 8*40);
                al[i][2] = *(const uint32_t*)(q + 8);
                al[i][3] = *(const uint32_t*)(q + 8*40 + 8);
            }
            #pragma unroll
            for (int j = 0; j < 8; j++) {
                const __nv_bfloat16* p = sB  + (warp_n*64 + j*8 + g)*40 + kk + 2*tg;
                const __nv_bfloat16* q = sBl + (warp_n*64 + j*8 + g)*40 + kk + 2*tg;
                uint32_t bh[2], bl[2];
                bh[0] = *(const uint32_t*)p;
                bh[1] = *(const uint32_t*)(p + 8);
                bl[0] = *(const uint32_t*)q;
                bl[1] = *(const uint32_t*)(q + 8);
                mma16816(acc[0][j], ah[0], bh);
                mma16816(acc[1][j], ah[1], bh);
                mma16816(acc[0][j], ah[0], bl);
                mma16816(acc[1][j], ah[1], bl);
                mma16816(acc[0][j], al[0], bh);
                mma16816(acc[1][j], al[1], bh);
            }
        }
        __syncthreads();
    }

    // epilogue
    float s = 0.f, s2 = 0.f;
    #pragma unroll
    for (int j = 0; j < 8; j++) {
        const int cc = n0 + warp_n*64 + j*8 + 2*tg;
        float b0 = 0.f, b1 = 0.f;
        if (which) { b0 = bias[cc]; b1 = bias[cc + 1]; }
        #pragma unroll
        for (int i = 0; i < 2; i++) {
            const long long r = r0 + warp_m*32 + i*16 + g;
            const float v0 = acc[i][j][0] + b0, v1 = acc[i][j][1] + b1;
            const float v2 = acc[i][j][2] + b0, v3 = acc[i][j][3] + b1;
            *(float2*)(&C[(size_t)r * ldc + cc])       = make_float2(v0, v1);
            *(float2*)(&C[(size_t)(r + 8) * ldc + cc]) = make_float2(v2, v3);
            if (which) {
                s  += v0 + v1 + v2 + v3;
                s2 += v0*v0 + v1*v1 + v2*v2 + v3*v3;
            }
        }
    }
    if (which) {
        // all lanes of a warp share one GN group (64-col aperture)
        #pragma unroll
        for (int off = 16; off > 0; off >>= 1) {
            s  += __shfl_xor_sync(0xffffffff, s,  off);
            s2 += __shfl_xor_sync(0xffffffff, s2, off);
        }
        if (lane == 0) {
            const int b = (int)(blockIdx.y >> 4);
            const int grp = (n0 >> 6) + warp_n;
            atomicAdd(&g_gnsum[(b * 8 + grp) * 2],     s);
            atomicAdd(&g_gnsum[(b * 8 + grp) * 2 + 1], s2);
        }
    }
}

// =====================================================================
// GLU + LayerNorm fused (warp per row)
// =====================================================================
__global__ void __launch_bounds__(256) glu_ln_kernel(
    const float* __restrict__ gb, const float* __restrict__ pb,
    const float* __restrict__ ln_w, const float* __restrict__ ln_b)
{
    const long long r = (long long)blockIdx.x * 8 + (threadIdx.x >> 5);
    const int lane = threadIdx.x & 31;
    float h[20];
    float s = 0.f, s2 = 0.f;
    #pragma unroll
    for (int j = 0; j < 20; j++) {
        const int c = lane + j * 32;
        const float gv = g_gp[r * 1280 + c] + gb[c];
        const float pv = g_gp[r * 1280 + 640 + c] + pb[c];
        const size_t ai = (size_t)r * DC + c;
        const float zse = __bfloat162float(g_ahi[ai]) + __bfloat162float(g_alo[ai]);
        const float sg = sigmoidf_(gv);
        h[j] = fmaf(sg, pv - zse, zse);
        s += h[j]; s2 += h[j] * h[j];
    }
    #pragma unroll
    for (int o = 16; o > 0; o >>= 1) {
        s  += __shfl_xor_sync(0xffffffff, s,  o);
        s2 += __shfl_xor_sync(0xffffffff, s2, o);
    }
    const float mu = s * (1.f / DC);
    const float var = fmaxf(s2 * (1.f / DC) - mu * mu, 0.f);
    const float rstd = rsqrtf(var + EPSF);
    #pragma unroll
    for (int j = 0; j < 20; j++) {
        const int c = lane + j * 32;
        const float val = (h[j] - mu) * rstd * ln_w[c] + ln_b[c];
        const __nv_bfloat16 hi = __float2bfloat16(val);
        g_ahi[r * DC + c] = hi;
        g_alo[r * DC + c] = __float2bfloat16(val - __bfloat162float(hi));
    }
}

// =====================================================================
// GroupNorm finalize + apply
// =====================================================================
__global__ void __launch_bounds__(512) gn_finalize_kernel()
{
    const int idx = threadIdx.x;
    if (idx < BB * 8) {
        const float inv = 1.f / (TT * 64.f);
        const float m = g_gnsum[idx * 2] * inv;
        const float var = fmaxf(g_gnsum[idx * 2 + 1] * inv - m * m, 0.f);
        g_gn[idx] = make_float2(m, rsqrtf(var + EPSF));
    }
}

__global__ void __launch_bounds__(256) gn_apply_kernel(
    float* __restrict__ out, const float* __restrict__ gn_w, const float* __restrict__ gn_b)
{
    const long long total4 = (long long)BT * DD / 4;
    for (long long i4 = (long long)blockIdx.x * blockDim.x + threadIdx.x;
         i4 < total4; i4 += (long long)gridDim.x * blockDim.x) {
        const long long i = i4 * 4;
        const int c = (int)(i & (DD - 1));
        const int b = (int)(i >> 20);
        const int g = c >> 6;
        const float2 mg = g_gn[b * 8 + g];
        float4 v = *(float4*)(out + i);
        v.x = (v.x - mg.x) * mg.y * gn_w[c]     + gn_b[c];
        v.y = (v.y - mg.x) * mg.y * gn_w[c + 1] + gn_b[c + 1];
        v.z = (v.z - mg.x) * mg.y * gn_w[c + 2] + gn_b[c + 2];
        v.w = (v.w - mg.x) * mg.y * gn_w[c + 3] + gn_b[c + 3];
        *(float4*)(out + i) = v;
    }
}

// =====================================================================
// launch
// =====================================================================
extern "C" void kernel_launch(void* const* d_in, const int* in_sizes, int n_in,
                              void* d_out, int out_size)
{
    const float* x    = (const float*)d_in[0];
    const float* hw1  = (const float*)d_in[1];
    const float* hb1  = (const float*)d_in[2];
    const float* hw2  = (const float*)d_in[3];
    const float* hb2  = (const float*)d_in[4];
    const float* lw1  = (const float*)d_in[5];
    const float* lb1  = (const float*)d_in[6];
    const float* lw2  = (const float*)d_in[7];
    const float* lb2  = (const float*)d_in[8];
    const float* ew1  = (const float*)d_in[9];
    const float* eb1  = (const float*)d_in[10];
    const float* ew2  = (const float*)d_in[11];
    const float* eb2  = (const float*)d_in[12];
    const float* sew1 = (const float*)d_in[13];
    const float* sew2 = (const float*)d_in[14];
    const float* gw   = (const float*)d_in[15];
    const float* gb   = (const float*)d_in[16];
    const float* pw   = (const float*)d_in[17];
    const float* pb   = (const float*)d_in[18];
    const float* lnw  = (const float*)d_in[19];
    const float* lnb  = (const float*)d_in[20];
    const float* ow   = (const float*)d_in[21];
    const float* ob   = (const float*)d_in[22];
    const float* gnw  = (const float*)d_in[23];
    const float* gnb  = (const float*)d_in[24];
    float* out = (float*)d_out;

    const int SMEM1A = 32 * CIN * 4;
    cudaFuncSetAttribute(stage1a_kernel, cudaFuncAttributeMaxDynamicSharedMemorySize, SMEM1A);
    cudaFuncSetAttribute(zgemm_kernel,   cudaFuncAttributeMaxDynamicSharedMemorySize, GEMM_SMEM);
    cudaFuncSetAttribute(gemm_kernel,    cudaFuncAttributeMaxDynamicSharedMemorySize, GEMM_SMEM);

    prep_w_kernel<<<(WROWS * DC + 255) / 256, 256>>>(gw, pw, ow);
    prep_aux_kernel<<<(640 * 256 + RED * DC + 255) / 256, 256>>>(hw2, lw2, ew2, sew1);
    zero_kernel<<<(BB * DC + 255) / 256, 256>>>();
    stage1a_kernel<<<BT / 32, 256, SMEM1A>>>(x, hw1, hb1, lw1, lb1, ew1, eb1);
    zgemm_kernel<<<dim3(5, BT / 128), 256, GEMM_SMEM>>>(hb2, lb2, eb2);
    se_mlp_kernel<<<BB, 256>>>(sew2);
    prep_a_kernel<<<8192, 256>>>();
    // gate GEMM: C = g_gp [BT,1280]
    gemm_kernel<<<dim3(10, BT / 128), 256, GEMM_SMEM>>>(0, 0, nullptr, 1280, nullptr);
    glu_ln_kernel<<<BT / 8, 256>>>(gb, pb, lnw, lnb);
    // out GEMM: C = out [BT,512] + ob, fused GN stats
    gemm_kernel<<<dim3(4, BT / 128), 256, GEMM_SMEM>>>(1280, 1, out, DD, ob);
    gn_finalize_kernel<<<1, 512>>>();
    gn_apply_kernel<<<4096, 256>>>(out, gnw, gnb);
}